// round 1
// baseline (speedup 1.0000x reference)
#include <cuda_runtime.h>
#include <cuda_bf16.h>
#include <cstdint>

// GaussianLayer: out[m,k] = tanh(scale[k]) * exp(-zz - mm + 2*zm)
//   d[k,i]  = 0.1 + 0.9*sigmoid(diag[k,i])
//   zz[m,k] = sum_i d[k,i]*z[m,i]^2
//   mm[k]   = sum_i d[k,i]*mean[k,i]^2
//   zm[m,k] = sum_i z[m,i]*d[k,i]*mean[k,i]
//
// exponent = -sum_i d[k,i]*(z[m,i]-mean[k,i])^2  <= 0  (exact identity)
// Weighted Cauchy-Schwarz lower bound on the distance (d in (0.1,1]):
//   sum d(z-m)^2 >= (sqrt(mm[k]) - ||z_m||)^2   when sqrt(mm[k]) >= ||z_m||
// If that bound exceeds ~104, expf underflows to exactly 0.0f, so we can
// write 0 without the K-dim reduction. Fallback computes the exact fp32
// reference expression for any element where the bound is insufficient.

#define MAX_M 16384
#define MAX_OUT 2048

__device__ float g_zn[MAX_M];    // ||z_m||
__device__ float g_mm[MAX_OUT];  // sum_i d*mean^2
__device__ float g_ts[MAX_OUT];  // tanh(scale)

// ---------------- Kernel 1: per-row L2 norm of z -------------------------
__global__ void __launch_bounds__(256) row_norm_kernel(
    const float* __restrict__ z, int m, int in_f)
{
    int warp = (blockIdx.x * blockDim.x + threadIdx.x) >> 5;
    int lane = threadIdx.x & 31;
    if (warp >= m) return;
    const float4* row = reinterpret_cast<const float4*>(z + (size_t)warp * in_f);
    int n4 = in_f >> 2;
    float s = 0.0f;
    for (int i = lane; i < n4; i += 32) {
        float4 v = row[i];
        s += v.x * v.x + v.y * v.y + v.z * v.z + v.w * v.w;
    }
    #pragma unroll
    for (int o = 16; o; o >>= 1) s += __shfl_xor_sync(0xFFFFFFFFu, s, o);
    if (lane == 0) g_zn[warp] = sqrtf(s);
}

// ---------------- Kernel 2: per-out-feature mm[k], tanh(scale[k]) --------
__global__ void __launch_bounds__(256) prep_k_kernel(
    const float* __restrict__ diag, const float* __restrict__ mean,
    const float* __restrict__ scale, int out_f, int in_f)
{
    int warp = (blockIdx.x * blockDim.x + threadIdx.x) >> 5;
    int lane = threadIdx.x & 31;
    if (warp >= out_f) return;
    const float4* dr = reinterpret_cast<const float4*>(diag + (size_t)warp * in_f);
    const float4* mr = reinterpret_cast<const float4*>(mean + (size_t)warp * in_f);
    int n4 = in_f >> 2;
    float s = 0.0f;
    for (int i = lane; i < n4; i += 32) {
        float4 dv = dr[i];
        float4 mv = mr[i];
        float d0 = 0.1f + 0.9f / (1.0f + expf(-dv.x));
        float d1 = 0.1f + 0.9f / (1.0f + expf(-dv.y));
        float d2 = 0.1f + 0.9f / (1.0f + expf(-dv.z));
        float d3 = 0.1f + 0.9f / (1.0f + expf(-dv.w));
        s += d0 * mv.x * mv.x + d1 * mv.y * mv.y + d2 * mv.z * mv.z + d3 * mv.w * mv.w;
    }
    #pragma unroll
    for (int o = 16; o; o >>= 1) s += __shfl_xor_sync(0xFFFFFFFFu, s, o);
    if (lane == 0) {
        g_mm[warp] = s;
        g_ts[warp] = tanhf(scale[warp]);
    }
}

// ---------------- Fallback: exact fp32 reference expression --------------
__device__ __noinline__ float slow_elem(
    const float* __restrict__ z, const float* __restrict__ diag,
    const float* __restrict__ mean, float mmk, float tsk,
    int mrow, int k, int in_f)
{
    const float* zr = z + (size_t)mrow * in_f;
    const float* dr = diag + (size_t)k * in_f;
    const float* mr = mean + (size_t)k * in_f;
    float zz = 0.0f, zm = 0.0f;
    for (int i = 0; i < in_f; i++) {
        float d = 0.1f + 0.9f / (1.0f + expf(-dr[i]));
        float zi = zr[i];
        float mi = mr[i];
        zz += d * zi * zi;
        zm += zi * d * mi;
    }
    return tsk * expf(-zz - mmk + 2.0f * zm);
}

// ---------------- Kernel 3: output --------------------------------------
// Bound margin: need (sqrt(mm)-zn)^2 > 110 > 104 => sqrt(mm) > zn + 10.5;
// use +12 to absorb all fp32 rounding in the norm reductions.
__global__ void __launch_bounds__(512) out_kernel(
    const float* __restrict__ z, const float* __restrict__ diag,
    const float* __restrict__ mean, float* __restrict__ out,
    int m, int out_f, int in_f)
{
    int mrow = blockIdx.x;
    float znv = g_zn[mrow];
    int k0 = (blockIdx.y * blockDim.x + threadIdx.x) * 4;
    if (k0 + 3 >= out_f) {
        // scalar tail (not hit for out_f multiple of 4*blockDim-coverage)
        for (int k = k0; k < out_f; k++) {
            float mmk = g_mm[k];
            float v = (sqrtf(mmk) > znv + 12.0f)
                          ? 0.0f
                          : slow_elem(z, diag, mean, mmk, g_ts[k], mrow, k, in_f);
            out[(size_t)mrow * out_f + k] = v;
        }
        return;
    }
    float4 mm4 = *reinterpret_cast<const float4*>(&g_mm[k0]);
    float4 r;
    r.x = (sqrtf(mm4.x) > znv + 12.0f) ? 0.0f
          : slow_elem(z, diag, mean, mm4.x, g_ts[k0 + 0], mrow, k0 + 0, in_f);
    r.y = (sqrtf(mm4.y) > znv + 12.0f) ? 0.0f
          : slow_elem(z, diag, mean, mm4.y, g_ts[k0 + 1], mrow, k0 + 1, in_f);
    r.z = (sqrtf(mm4.z) > znv + 12.0f) ? 0.0f
          : slow_elem(z, diag, mean, mm4.z, g_ts[k0 + 2], mrow, k0 + 2, in_f);
    r.w = (sqrtf(mm4.w) > znv + 12.0f) ? 0.0f
          : slow_elem(z, diag, mean, mm4.w, g_ts[k0 + 3], mrow, k0 + 3, in_f);
    *reinterpret_cast<float4*>(&out[(size_t)mrow * out_f + k0]) = r;
}

extern "C" void kernel_launch(void* const* d_in, const int* in_sizes, int n_in,
                              void* d_out, int out_size)
{
    const float* z     = (const float*)d_in[0];  // (m, in_f)
    const float* diag  = (const float*)d_in[1];  // (out_f, in_f)
    const float* mean  = (const float*)d_in[2];  // (out_f, in_f, 1) == (out_f, in_f)
    const float* scale = (const float*)d_in[3];  // (out_f,)
    float* out = (float*)d_out;

    int out_f = in_sizes[3];
    int in_f  = in_sizes[1] / out_f;
    int m     = in_sizes[0] / in_f;

    // Kernel 1: one warp per m-row
    {
        int warps = m;
        int threads = 256;
        int blocks = (warps * 32 + threads - 1) / threads;
        row_norm_kernel<<<blocks, threads>>>(z, m, in_f);
    }
    // Kernel 2: one warp per k-row
    {
        int warps = out_f;
        int threads = 256;
        int blocks = (warps * 32 + threads - 1) / threads;
        prep_k_kernel<<<blocks, threads>>>(diag, mean, scale, out_f, in_f);
    }
    // Kernel 3: one block per m-row, 512 threads x 4 floats covers out_f=2048
    {
        int threads = 512;
        int per_block = threads * 4;
        dim3 grid(m, (out_f + per_block - 1) / per_block);
        out_kernel<<<grid, threads>>>(z, diag, mean, out, m, out_f, in_f);
    }
}

// round 2
// speedup vs baseline: 1.5285x; 1.5285x over previous
#include <cuda_runtime.h>
#include <cuda_bf16.h>
#include <cstdint>
#include <cfloat>

// GaussianLayer: out[m,k] = tanh(scale[k]) * exp(-zz - mm + 2*zm)
//   d[k,i]  = 0.1 + 0.9*sigmoid(diag[k,i]),  d in (0.1, 1.0)
//   exponent = -sum_i d[k,i]*(z[m,i]-mean[k,i])^2  <= 0 (exact identity)
// Weighted Cauchy-Schwarz (with d <= 1):
//   sum_i d*(z-mean)^2 >= (sqrt(mm[k]) - ||z_m||)^2   when sqrt(mm[k]) >= ||z_m||
// If sqrt(mm[k]) > ||z_m|| + 12, the exponent is < -144 < -104, expf
// underflows to exactly +0.0f, so tanh(scale)*exp(..) == +-0.0f and we can
// write 0 without any K-dim reduction. Elements failing the bound fall back
// to the exact fp32 reference expression.

#define MAX_M 16384
#define MAX_OUT 2048

__device__ float g_zn[MAX_M];    // ||z_m||
__device__ float g_sq[MAX_OUT];  // sqrt(sum_i d*mean^2)
__device__ float g_ts[MAX_OUT];  // tanh(scale)

// ================= Kernel A: fused prep (row norms + k-stats) ============
// Blocks [0, nb_m): row norms, one warp per m-row (8 rows/block).
// Blocks [nb_m, nb_m+nb_k): k-stats, one warp per out-feature.
__global__ void __launch_bounds__(256) prep_kernel(
    const float* __restrict__ z,
    const float* __restrict__ diag, const float* __restrict__ mean,
    const float* __restrict__ scale,
    int m, int out_f, int in_f, int nb_m)
{
    int wid_in_blk = threadIdx.x >> 5;
    int lane = threadIdx.x & 31;
    int n4 = in_f >> 2;

    if (blockIdx.x < nb_m) {
        // ---- row norm of z ----
        int row = blockIdx.x * 8 + wid_in_blk;
        if (row >= m) return;
        const float4* r = reinterpret_cast<const float4*>(z + (size_t)row * in_f);
        float s = 0.0f;
        if (n4 == 256) {
            // in_f == 1024: 8 fully independent loads per lane (MLP=8)
            float4 v[8];
            #pragma unroll
            for (int j = 0; j < 8; j++) v[j] = __ldcs(&r[lane + 32 * j]);
            #pragma unroll
            for (int j = 0; j < 8; j++)
                s += v[j].x * v[j].x + v[j].y * v[j].y
                   + v[j].z * v[j].z + v[j].w * v[j].w;
        } else {
            for (int i = lane; i < n4; i += 32) {
                float4 v = __ldcs(&r[i]);
                s += v.x * v.x + v.y * v.y + v.z * v.z + v.w * v.w;
            }
        }
        #pragma unroll
        for (int o = 16; o; o >>= 1) s += __shfl_xor_sync(0xFFFFFFFFu, s, o);
        if (lane == 0) g_zn[row] = sqrtf(s);
    } else {
        // ---- per-out-feature: sqrt(sum d*mean^2), tanh(scale) ----
        int k = (blockIdx.x - nb_m) * 8 + wid_in_blk;
        if (k >= out_f) return;
        const float4* dr = reinterpret_cast<const float4*>(diag + (size_t)k * in_f);
        const float4* mr = reinterpret_cast<const float4*>(mean + (size_t)k * in_f);
        float s = 0.0f;
        #pragma unroll 4
        for (int i = lane; i < n4; i += 32) {
            float4 dv = __ldcs(&dr[i]);
            float4 mv = __ldcs(&mr[i]);
            float d0 = 0.1f + 0.9f / (1.0f + expf(-dv.x));
            float d1 = 0.1f + 0.9f / (1.0f + expf(-dv.y));
            float d2 = 0.1f + 0.9f / (1.0f + expf(-dv.z));
            float d3 = 0.1f + 0.9f / (1.0f + expf(-dv.w));
            s += d0 * mv.x * mv.x + d1 * mv.y * mv.y
               + d2 * mv.z * mv.z + d3 * mv.w * mv.w;
        }
        #pragma unroll
        for (int o = 16; o; o >>= 1) s += __shfl_xor_sync(0xFFFFFFFFu, s, o);
        if (lane == 0) {
            g_sq[k] = sqrtf(s);
            g_ts[k] = tanhf(scale[k]);
        }
    }
}

// ================= Fallback: exact fp32 reference expression ==============
__device__ __noinline__ float slow_elem(
    const float* __restrict__ z, const float* __restrict__ diag,
    const float* __restrict__ mean, float sqk, float tsk,
    int mrow, int k, int in_f)
{
    const float* zr = z + (size_t)mrow * in_f;
    const float* dr = diag + (size_t)k * in_f;
    const float* mr = mean + (size_t)k * in_f;
    float zz = 0.0f, zm = 0.0f;
    for (int i = 0; i < in_f; i++) {
        float d = 0.1f + 0.9f / (1.0f + expf(-dr[i]));
        float zi = zr[i];
        float mi = mr[i];
        zz += d * zi * zi;
        zm += zi * d * mi;
    }
    float mmk = sqk * sqk;
    return tsk * expf(-zz - mmk + 2.0f * zm);
}

// ================= Kernel B: output =======================================
// One block (256 threads) handles ROWS_PER_BLOCK m-rows x all out_f k's.
// Loads sqrt_mm into smem ONCE, computes block min ONCE; rows passing the
// min-test are pure streaming float4 zero-stores.
#define ROWS_PER_BLOCK 16

__global__ void __launch_bounds__(256) out_kernel(
    const float* __restrict__ z, const float* __restrict__ diag,
    const float* __restrict__ mean, float* __restrict__ out,
    int m, int out_f, int in_f)
{
    __shared__ float s_sq[MAX_OUT];
    __shared__ float s_wmin[8];
    __shared__ float s_min;

    int tid = threadIdx.x;
    int lane = tid & 31;
    int wid = tid >> 5;

    // Load sqrt_mm tile + local min
    float lm = FLT_MAX;
    for (int k = tid; k < out_f; k += 256) {
        float v = g_sq[k];
        s_sq[k] = v;
        lm = fminf(lm, v);
    }
    #pragma unroll
    for (int o = 16; o; o >>= 1) lm = fminf(lm, __shfl_xor_sync(0xFFFFFFFFu, lm, o));
    if (lane == 0) s_wmin[wid] = lm;
    __syncthreads();
    if (tid == 0) {
        float mv = s_wmin[0];
        #pragma unroll
        for (int i = 1; i < 8; i++) mv = fminf(mv, s_wmin[i]);
        s_min = mv;
    }
    __syncthreads();
    float blkmin = s_min;

    int row0 = blockIdx.x * ROWS_PER_BLOCK;
    int n4 = out_f >> 2;
    const float4 zero4 = make_float4(0.0f, 0.0f, 0.0f, 0.0f);

    #pragma unroll
    for (int r = 0; r < ROWS_PER_BLOCK; r++) {
        int row = row0 + r;
        if (row >= m) return;
        float thr = g_zn[row] + 12.0f;
        float4* orow4 = reinterpret_cast<float4*>(out + (size_t)row * out_f);
        if (blkmin > thr) {
            // Entire row provably underflows: streaming zero stores.
            for (int k4 = tid; k4 < n4; k4 += 256)
                __stcs(&orow4[k4], zero4);
        } else {
            // Mixed row: per-element bound test, exact fallback when needed.
            for (int k = tid; k < out_f; k += 256) {
                float v = (s_sq[k] > thr)
                              ? 0.0f
                              : slow_elem(z, diag, mean, s_sq[k], g_ts[k],
                                          row, k, in_f);
                out[(size_t)row * out_f + k] = v;
            }
        }
    }
}

extern "C" void kernel_launch(void* const* d_in, const int* in_sizes, int n_in,
                              void* d_out, int out_size)
{
    const float* z     = (const float*)d_in[0];  // (m, in_f)
    const float* diag  = (const float*)d_in[1];  // (out_f, in_f)
    const float* mean  = (const float*)d_in[2];  // (out_f, in_f, 1)
    const float* scale = (const float*)d_in[3];  // (out_f,)
    float* out = (float*)d_out;

    int out_f = in_sizes[3];
    int in_f  = in_sizes[1] / out_f;
    int m     = in_sizes[0] / in_f;

    // Kernel A: fused prep. 8 warps/block; row-norm blocks then k-stat blocks.
    int nb_m = (m + 7) / 8;
    int nb_k = (out_f + 7) / 8;
    prep_kernel<<<nb_m + nb_k, 256>>>(z, diag, mean, scale, m, out_f, in_f, nb_m);

    // Kernel B: output, 16 rows per 256-thread block.
    int nb_out = (m + ROWS_PER_BLOCK - 1) / ROWS_PER_BLOCK;
    out_kernel<<<nb_out, 256>>>(z, diag, mean, out, m, out_f, in_f);
}

// round 3
// speedup vs baseline: 1.7420x; 1.1396x over previous
#include <cuda_runtime.h>
#include <cuda_bf16.h>
#include <cstdint>
#include <cfloat>

// GaussianLayer: out[m,k] = tanh(scale[k]) * exp(-zz - mm + 2*zm)
//   d[k,i]  = 0.1 + 0.9*sigmoid(diag[k,i]),  d in (0.1, 1.0)
//   exponent = -sum_i d[k,i]*(z[m,i]-mean[k,i])^2  <= 0 (exact identity)
// Weighted Cauchy-Schwarz (with d <= 1):
//   sum_i d*(z-mean)^2 >= (sqrt(mm[k]) - ||z_m||)^2  when sqrt(mm[k]) >= ||z_m||
// If sqrt(mm[k]) > ||z_m|| + 12, exponent < -144 < -104 => expf underflows
// to exactly +-0.0f. Elements failing the bound use the exact fp32 reference
// expression. The +12 margin dwarfs any rounding in the norm computations,
// so fast sigmoid approximations in the bound are safe.

#define MAX_M 16384
#define MAX_OUT 2048

__device__ float g_zn[MAX_M];    // ||z_m||
__device__ float g_sq[MAX_OUT];  // sqrt(sum_i d*mean^2)
__device__ float g_ts[MAX_OUT];  // tanh(scale)
__device__ float g_minsq;        // min_k g_sq[k]

// ================= Kernel A: fused prep (row norms + k-stats) ============
__global__ void __launch_bounds__(256) prep_kernel(
    const float* __restrict__ z,
    const float* __restrict__ diag, const float* __restrict__ mean,
    const float* __restrict__ scale,
    int m, int out_f, int in_f, int nb_m)
{
    int wid_in_blk = threadIdx.x >> 5;
    int lane = threadIdx.x & 31;
    int n4 = in_f >> 2;

    if (blockIdx.x < nb_m) {
        // ---- row norm of z (8 independent float4 loads per lane) ----
        int row = blockIdx.x * 8 + wid_in_blk;
        if (row >= m) return;
        const float4* r = reinterpret_cast<const float4*>(z + (size_t)row * in_f);
        float s = 0.0f;
        if (n4 == 256) {
            float4 v[8];
            #pragma unroll
            for (int j = 0; j < 8; j++) v[j] = __ldcs(&r[lane + 32 * j]);
            #pragma unroll
            for (int j = 0; j < 8; j++)
                s += v[j].x * v[j].x + v[j].y * v[j].y
                   + v[j].z * v[j].z + v[j].w * v[j].w;
        } else {
            for (int i = lane; i < n4; i += 32) {
                float4 v = __ldcs(&r[i]);
                s += v.x * v.x + v.y * v.y + v.z * v.z + v.w * v.w;
            }
        }
        #pragma unroll
        for (int o = 16; o; o >>= 1) s += __shfl_xor_sync(0xFFFFFFFFu, s, o);
        if (lane == 0) g_zn[row] = sqrtf(s);
    } else {
        // ---- per-out-feature: sqrt(sum d*mean^2), tanh(scale) ----
        // Fast sigmoid (__expf + __fdividef): feeds only the conservative
        // bound (huge margin) -- the exact fallback path never uses these.
        int k = (blockIdx.x - nb_m) * 8 + wid_in_blk;
        if (k >= out_f) return;
        const float4* dr = reinterpret_cast<const float4*>(diag + (size_t)k * in_f);
        const float4* mr = reinterpret_cast<const float4*>(mean + (size_t)k * in_f);
        float s = 0.0f;
        #pragma unroll 4
        for (int i = lane; i < n4; i += 32) {
            float4 dv = __ldcs(&dr[i]);
            float4 mv = __ldcs(&mr[i]);
            float d0 = 0.1f + __fdividef(0.9f, 1.0f + __expf(-dv.x));
            float d1 = 0.1f + __fdividef(0.9f, 1.0f + __expf(-dv.y));
            float d2 = 0.1f + __fdividef(0.9f, 1.0f + __expf(-dv.z));
            float d3 = 0.1f + __fdividef(0.9f, 1.0f + __expf(-dv.w));
            s += d0 * mv.x * mv.x + d1 * mv.y * mv.y
               + d2 * mv.z * mv.z + d3 * mv.w * mv.w;
        }
        #pragma unroll
        for (int o = 16; o; o >>= 1) s += __shfl_xor_sync(0xFFFFFFFFu, s, o);
        if (lane == 0) {
            g_sq[k] = sqrtf(s);
            g_ts[k] = tanhf(scale[k]);
        }
    }
}

// ================= Kernel C: single-block min over g_sq ===================
__global__ void __launch_bounds__(256) minsq_kernel(int out_f)
{
    __shared__ float s_w[8];
    int tid = threadIdx.x;
    float lm = FLT_MAX;
    for (int k = tid; k < out_f; k += 256) lm = fminf(lm, g_sq[k]);
    #pragma unroll
    for (int o = 16; o; o >>= 1) lm = fminf(lm, __shfl_xor_sync(0xFFFFFFFFu, lm, o));
    if ((tid & 31) == 0) s_w[tid >> 5] = lm;
    __syncthreads();
    if (tid == 0) {
        float mv = s_w[0];
        #pragma unroll
        for (int i = 1; i < 8; i++) mv = fminf(mv, s_w[i]);
        g_minsq = mv;
    }
}

// ================= Fallback: exact fp32 reference expression ==============
__device__ __noinline__ float slow_elem(
    const float* __restrict__ z, const float* __restrict__ diag,
    const float* __restrict__ mean, int mrow, int k, int in_f)
{
    const float* zr = z + (size_t)mrow * in_f;
    const float* dr = diag + (size_t)k * in_f;
    const float* mr = mean + (size_t)k * in_f;
    float zz = 0.0f, zm = 0.0f, mm = 0.0f;
    for (int i = 0; i < in_f; i++) {
        float d = 0.1f + 0.9f / (1.0f + expf(-dr[i]));
        float zi = zr[i];
        float mi = mr[i];
        zz += d * zi * zi;
        zm += zi * d * mi;
        mm += d * mi * mi;
    }
    return g_ts[k] * expf(-zz - mm + 2.0f * zm);
}

// ================= Kernel B: flat streaming output ========================
// Each block owns a contiguous tile of 256*OUT_UNROLL float4s. Each thread:
// 8 independent {row lookup (L1 hit), bound test, STG.128}. No smem/syncs.
#define OUT_UNROLL 8

__global__ void __launch_bounds__(256) out_kernel(
    const float* __restrict__ z, const float* __restrict__ diag,
    const float* __restrict__ mean, float* __restrict__ out,
    int m, int out_f, int in_f, int n4row, int n4tot, int row_shift)
{
    float minsq = g_minsq;
    int base = blockIdx.x * (256 * OUT_UNROLL) + threadIdx.x;
    const float4 zero4 = make_float4(0.0f, 0.0f, 0.0f, 0.0f);

    int   i4[OUT_UNROLL];
    int   row[OUT_UNROLL];
    float thr[OUT_UNROLL];
    bool  valid[OUT_UNROLL];

    #pragma unroll
    for (int j = 0; j < OUT_UNROLL; j++) {
        i4[j] = base + j * 256;
        valid[j] = i4[j] < n4tot;
        int r = valid[j]
                    ? (row_shift >= 0 ? (i4[j] >> row_shift)
                                      : (int)((unsigned)i4[j] / (unsigned)n4row))
                    : 0;
        row[j] = r;
        thr[j] = g_zn[r] + 12.0f;   // 8 independent L1-resident loads
    }

    #pragma unroll
    for (int j = 0; j < OUT_UNROLL; j++) {
        if (!valid[j]) continue;
        if (minsq > thr[j]) {
            __stcs(reinterpret_cast<float4*>(out) + i4[j], zero4);
        } else {
            // Rare mixed row: per-element bound test + exact fallback.
            int kbase = (i4[j] - row[j] * n4row) * 4;
            float4 r4;
            float* rp = &r4.x;
            #pragma unroll
            for (int e = 0; e < 4; e++) {
                int k = kbase + e;
                rp[e] = (g_sq[k] > thr[j])
                            ? 0.0f
                            : slow_elem(z, diag, mean, row[j], k, in_f);
            }
            reinterpret_cast<float4*>(out)[i4[j]] = r4;
        }
    }
}

extern "C" void kernel_launch(void* const* d_in, const int* in_sizes, int n_in,
                              void* d_out, int out_size)
{
    const float* z     = (const float*)d_in[0];  // (m, in_f)
    const float* diag  = (const float*)d_in[1];  // (out_f, in_f)
    const float* mean  = (const float*)d_in[2];  // (out_f, in_f, 1)
    const float* scale = (const float*)d_in[3];  // (out_f,)
    float* out = (float*)d_out;

    int out_f = in_sizes[3];
    int in_f  = in_sizes[1] / out_f;
    int m     = in_sizes[0] / in_f;

    // Kernel A: fused prep (row norms + k stats)
    int nb_m = (m + 7) / 8;
    int nb_k = (out_f + 7) / 8;
    prep_kernel<<<nb_m + nb_k, 256>>>(z, diag, mean, scale, m, out_f, in_f, nb_m);

    // Kernel C: global min of sqrt(mm)
    minsq_kernel<<<1, 256>>>(out_f);

    // Kernel B: flat streaming output
    int n4row = out_f >> 2;
    int n4tot = (int)(((size_t)m * out_f) >> 2);
    int row_shift = -1;
    if ((n4row & (n4row - 1)) == 0) {
        row_shift = 0;
        while ((1 << row_shift) != n4row) row_shift++;
    }
    int per_block = 256 * OUT_UNROLL;
    int nb_out = (n4tot + per_block - 1) / per_block;
    out_kernel<<<nb_out, 256>>>(z, diag, mean, out, m, out_f, in_f,
                                n4row, n4tot, row_shift);
}